// round 11
// baseline (speedup 1.0000x reference)
#include <cuda_runtime.h>
#include <cstdint>

// Embedding gather: out[i, :] = table[indices[i], :]
// indices: int32[4194304], table: float32[1000000, 16], out: float32[4194304, 16]
//
// Journal:
//   R4 BEST 77.9us: 2 threads/row, v8 table loads, streaming STG (405MB @ 5.25TB/s).
//   R6 L2 evict_last: no-op. R7 MLP x4: regress (L1tex queue). R8 1thr/row:
//   regress. R9 vocab tiling: regress (half-empty warps). R10 idx dedup: neutral.
//   DRAM busy stuck at 66% => L1tex-queue underfeed, stores are ~2M wavefronts.
//
// This round: keep R4's gather; move STORES off the L1tex path. Each warp
// gathers 16 rows (1 KB) into a private smem slice, then one lane issues a
// cp.async.bulk (smem -> gmem, UBLKCP) store. Per-warp double buffer with
// cp.async.bulk.wait_group.read — no block syncs. 1-deep prefetch of the next
// iteration's idx+v8 overlaps LDG latency with staging/stores.

struct __align__(32) f8 { float4 a, b; };

__device__ __forceinline__ f8 ldg_nc_f8(const f8* p) {
    f8 v;
    asm volatile(
        "ld.global.nc.v8.f32 {%0,%1,%2,%3,%4,%5,%6,%7}, [%8];"
        : "=f"(v.a.x), "=f"(v.a.y), "=f"(v.a.z), "=f"(v.a.w),
          "=f"(v.b.x), "=f"(v.b.y), "=f"(v.b.z), "=f"(v.b.w)
        : "l"(p));
    return v;
}

__device__ __forceinline__ uint32_t smem_u32(const void* p) {
    uint32_t a;
    asm("{ .reg .u64 t; cvta.to.shared.u64 t, %1; cvt.u32.u64 %0, t; }"
        : "=r"(a) : "l"(p));
    return a;
}

static constexpr int WARPS_PER_BLOCK = 8;
static constexpr int STAGES          = 2;
static constexpr int BYTES_PER_ITER  = 1024;   // 32 lanes x 32 B = 16 rows

__global__ void __launch_bounds__(256) gather_kernel(
    const int* __restrict__ indices,
    const f8* __restrict__ table8,      // table as 32 B chunks: 2 per row
    char* __restrict__ out_bytes,
    int total_warp_iters)               // total_chunks / 32
{
    __shared__ __align__(128) char smem[WARPS_PER_BLOCK * STAGES * BYTES_PER_ITER];

    int lane = threadIdx.x & 31;
    int w    = threadIdx.x >> 5;
    char* my_smem = smem + w * STAGES * BYTES_PER_ITER;

    int gw        = blockIdx.x * WARPS_PER_BLOCK + w;
    int num_warps = gridDim.x * WARPS_PER_BLOCK;

    // ---- prefetch iteration gw ----
    int wi = gw;
    f8 v_cur;
    bool have = (wi < total_warp_iters);
    if (have) {
        int j   = wi * 32 + lane;
        int idx = __ldcs(&indices[j >> 1]);
        v_cur   = ldg_nc_f8(&table8[(long long)idx * 2 + (j & 1)]);
    }

    int local_it = 0;
    while (have) {
        int wi_next = wi + num_warps;
        bool have_next = (wi_next < total_warp_iters);

        // ---- issue next iteration's loads (overlap with staging/store) ----
        f8 v_next;
        if (have_next) {
            int jn  = wi_next * 32 + lane;
            int idn = __ldcs(&indices[jn >> 1]);
            v_next  = ldg_nc_f8(&table8[(long long)idn * 2 + (jn & 1)]);
        }

        // ---- stage current into smem slice (double buffered) ----
        int s = local_it & (STAGES - 1);
        char* slice = my_smem + s * BYTES_PER_ITER;
        if (local_it >= STAGES) {
            // ensure the bulk store issued 2 iters ago finished READING slice s
            if (lane == 0)
                asm volatile("cp.async.bulk.wait_group.read %0;" :: "n"(STAGES - 1) : "memory");
            __syncwarp();
        }
        *reinterpret_cast<float4*>(slice + lane * 32 + 0)  = v_cur.a;
        *reinterpret_cast<float4*>(slice + lane * 32 + 16) = v_cur.b;
        __syncwarp();

        // ---- one bulk store per warp-iter: smem -> gmem, off the LSU path ----
        if (lane == 0) {
            asm volatile("fence.proxy.async.shared::cta;" ::: "memory");
            char* gdst = out_bytes + (long long)wi * BYTES_PER_ITER;
            asm volatile(
                "cp.async.bulk.global.shared::cta.bulk_group [%0], [%1], %2;"
                :: "l"(gdst), "r"(smem_u32(slice)), "r"(BYTES_PER_ITER)
                : "memory");
            asm volatile("cp.async.bulk.commit_group;" ::: "memory");
        }

        v_cur = v_next;
        wi    = wi_next;
        have  = have_next;
        local_it++;
    }

    // drain all outstanding bulk stores
    if (lane == 0)
        asm volatile("cp.async.bulk.wait_group.read 0;" ::: "memory");
}

extern "C" void kernel_launch(void* const* d_in, const int* in_sizes, int n_in,
                              void* d_out, int out_size)
{
    // Resolve input order by size: indices = 4,194,304 elems, table = 16,000,000.
    int idx_slot = 0, tab_slot = 1;
    if (n_in >= 2 && in_sizes[0] > in_sizes[1]) { idx_slot = 1; tab_slot = 0; }

    const int* indices = (const int*)d_in[idx_slot];
    const f8*  table8  = (const f8*)d_in[tab_slot];
    char*      out     = (char*)d_out;

    int num_indices     = in_sizes[idx_slot];        // 4,194,304
    int total_chunks    = num_indices * 2;           // 8,388,608 (32 B chunks)
    int total_warp_iters = total_chunks / 32;        // 262,144 (exactly divisible)

    int threads = 256;
    int blocks  = 2048;   // 16384 warps -> 16 iterations each
    gather_kernel<<<blocks, threads>>>(indices, table8, out, total_warp_iters);
}

// round 12
// speedup vs baseline: 1.0937x; 1.0937x over previous
#include <cuda_runtime.h>
#include <cstdint>

// Embedding gather: out[i, :] = table[indices[i], :]
// indices: int32[4194304], table: float32[1000000, 16], out: float32[4194304, 16]
//
// Journal:
//   R4 BEST 77.9us: 2 threads/row, v8 table loads, __stcs stores (405MB @ 5.25TB/s).
//   R6 L2 evict_last: no-op. R7 MLP x4: regress. R8 1thr/row: regress.
//   R9 vocab tiling: traffic down, BW down more. R10 idx dedup: neutral.
//   R11 bulk-store offload: L1 relieved, TMA active, still 67% DRAM -> regress.
//   Conclusion: wall = table reuse misses; the 256MB store stream ALLOCATES in
//   L2 and churns the 64MB table out (~50% hit).
//
// This round = R4 with ONE change: stores are st.global.wt (write-through, no
// L2 allocation). Output stream stops competing for L2 -> table approaches
// full residency -> table DRAM reads ~133MB -> ~70MB.

struct __align__(32) f8 { float4 a, b; };

__device__ __forceinline__ f8 ldg_nc_f8(const f8* p) {
    f8 v;
    asm volatile(
        "ld.global.nc.v8.f32 {%0,%1,%2,%3,%4,%5,%6,%7}, [%8];"
        : "=f"(v.a.x), "=f"(v.a.y), "=f"(v.a.z), "=f"(v.a.w),
          "=f"(v.b.x), "=f"(v.b.y), "=f"(v.b.z), "=f"(v.b.w)
        : "l"(p));
    return v;
}

__device__ __forceinline__ void stg_wt_f4(float4* p, float4 v) {
    asm volatile("st.global.wt.v4.f32 [%0], {%1,%2,%3,%4};"
                 :: "l"(p), "f"(v.x), "f"(v.y), "f"(v.z), "f"(v.w)
                 : "memory");
}

static constexpr int ROW_HALVES = 2;   // 16 floats = 2 x 32 B halves per row

__global__ void __launch_bounds__(256) gather_kernel(
    const int* __restrict__ indices,
    const f8* __restrict__ table8,     // table as 32 B chunks: 2 per row
    float4* __restrict__ out4,
    int total_chunks)
{
    int j = blockIdx.x * blockDim.x + threadIdx.x;   // 32 B chunk id
    if (j >= total_chunks) return;

    int row = j >> 1;          // output row
    int sub = j & 1;           // which 32 B half of the row

    long long idx = (long long)__ldcs(&indices[row]);
    f8 v = ldg_nc_f8(&table8[idx * ROW_HALVES + sub]);

    // write-through stores: no L2 allocation, table keeps the whole L2
    stg_wt_f4(&out4[j * 2 + 0], v.a);
    stg_wt_f4(&out4[j * 2 + 1], v.b);
}

extern "C" void kernel_launch(void* const* d_in, const int* in_sizes, int n_in,
                              void* d_out, int out_size)
{
    // Resolve input order by size: indices = 4,194,304 elems, table = 16,000,000.
    int idx_slot = 0, tab_slot = 1;
    if (n_in >= 2 && in_sizes[0] > in_sizes[1]) { idx_slot = 1; tab_slot = 0; }

    const int* indices = (const int*)d_in[idx_slot];
    const f8*  table8  = (const f8*)d_in[tab_slot];
    float4*    out4    = (float4*)d_out;

    int num_indices  = in_sizes[idx_slot];           // 4,194,304
    int total_chunks = num_indices * ROW_HALVES;     // 8,388,608

    int threads = 256;
    int blocks  = (total_chunks + threads - 1) / threads;   // 32768
    gather_kernel<<<blocks, threads>>>(indices, table8, out4, total_chunks);
}